// round 3
// baseline (speedup 1.0000x reference)
#include <cuda_runtime.h>

#define TPB  256
#define ROWS 64
#define XSTR 145   // activation buffer row stride (odd -> conflict-free column reads)
#define SSTR 51    // state tile row stride

// ---- embedding-region offsets inside smem (floats) ----
enum {
  EO_SUIT = 0,        // 5  x 8
  EO_RANK = 40,       // 14 x 8
  EO_POS = 152,       // 7  x 8
  EO_ACTION = 208,    // 12 x 8
  EO_ACTIVE = 304,    // 2  x 8
  EO_STREET = 320,    // 5  x 8
  EO_NUMP = 360,      // 7  x 8
  EO_BLIND = 416,     // 2  x 8
  EO_SW = 432,        // 6  x 8 scalar_W
  EO_SB = 480,        // 6  x 8 scalar_b
  EO_TOTAL = 528
};

// 31 output segments of 8 floats each, after the 64 hand_board dims.
// base >= 0 : embedding table offset in embS ; base < 0 : scalar proj, widx = -base-1
__constant__ int c_seg_base[31] = {
  EO_STREET, EO_POS,
  EO_ACTIVE, EO_ACTIVE, EO_ACTIVE, EO_ACTIVE, EO_ACTIVE,
  EO_POS, EO_POS, EO_POS, EO_POS, EO_POS,
  -1, -3, -4, -6,                // proj widx 0,2,3,5
  EO_POS, EO_ACTION, EO_BLIND,
  -2,                            // proj widx 1
  EO_ACTION, EO_POS, EO_BLIND,
  EO_NUMP, EO_POS,
  -5, -5, -5, -5, -5, -5         // proj widx 4 x6
};
__constant__ int c_seg_col[31] = {
  18, 20,
  22, 23, 24, 25, 26,
  27, 28, 29, 30, 31,
  40, 41, 42, 43,
  35, 36, 37,
  39,
  32, 33, 34,
  19, 38,
  44, 45, 46, 47, 48, 49
};

struct Params {
  const float* state;
  const float* suit_emb; const float* rank_emb;
  const float *hW1, *hb1, *hW2, *hb2, *hW3, *hb3;
  const float *bW1, *bb1, *bW2, *bb2, *bW3, *bb3;
  const float *cW1, *cb1, *cW2, *cb2, *cW3, *cb3;
  const float *pos_emb, *action_emb, *active_emb, *street_emb, *nump_emb, *blind_emb;
  const float *scalar_W, *scalar_b;
  float* out;
  int nrows;
};

__device__ __forceinline__ void cp_f(float* dst, const float* __restrict__ src, int n, int tid) {
  for (int e = tid; e < n; e += TPB) dst[e] = src[e];
}
__device__ __forceinline__ void cp_f4(float* dst, const float* __restrict__ src, int n, int tid) {
  float4* d4 = reinterpret_cast<float4*>(dst);
  const float4* s4 = reinterpret_cast<const float4*>(src);
  for (int e = tid; e < (n >> 2); e += TPB) d4[e] = s4[e];
}

// 64 rows x N cols = (X[64,K] @ W[K,N]) + b, optional leaky_relu(0.01).
// 256 threads as 16 colblocks (CB cols each) x 16 rowblocks (4 rows each).
// FMA:LDS per k-step = 4*CB : (4+CB)  -> >= 2.0, so FFMA pipe binds.
template<int K, int N, int CB, bool LEAKY>
__device__ __forceinline__ void gemm_tile(const float* __restrict__ Xs, float* __restrict__ Ys,
                                          const float* __restrict__ Ws, const float* __restrict__ Bs,
                                          int tid)
{
  const int cb = tid & 15;
  const int rb = tid >> 4;
  float acc[4][CB];
#pragma unroll
  for (int i = 0; i < 4; ++i)
#pragma unroll
    for (int j = 0; j < CB; ++j) acc[i][j] = 0.f;

  const float* xr = Xs + rb * 4 * XSTR;
#pragma unroll 4
  for (int k = 0; k < K; ++k) {
    float w[CB];
    if (CB == 4) {  // N multiple of 64: aligned vector load (dead-code-eliminated otherwise)
      float4 wv = *reinterpret_cast<const float4*>(Ws + k * N + cb * 4);
      w[0] = wv.x; w[1] = wv.y; w[2] = wv.z; w[3] = wv.w;
    } else {        // CB=5/9: stride-5/9 columns hit 16 distinct banks -> conflict-free
#pragma unroll
      for (int j = 0; j < CB; ++j) w[j] = Ws[k * N + cb * CB + j];
    }
#pragma unroll
    for (int i = 0; i < 4; ++i) {
      float x = xr[i * XSTR + k];
#pragma unroll
      for (int j = 0; j < CB; ++j) acc[i][j] = fmaf(x, w[j], acc[i][j]);
    }
  }
#pragma unroll
  for (int i = 0; i < 4; ++i)
#pragma unroll
    for (int j = 0; j < CB; ++j) {
      float v = acc[i][j] + Bs[cb * CB + j];
      if (LEAKY) v = (v >= 0.f) ? v : 0.01f * v;
      Ys[(rb * 4 + i) * XSTR + cb * CB + j] = v;
    }
}

__global__ void __launch_bounds__(TPB)
PreProcess_kernel(Params p)
{
  extern __shared__ float sm[];
  float* stateS = sm;                                   // 64*51   = 3264
  float* X      = sm + ROWS * SSTR;                     // 64*145  = 9280
  float* Y      = X + ROWS * XSTR;                      // 64*145  = 9280
  float* Ws     = Y + ROWS * XSTR;                      // 144*144 = 20736 (max layer)
  float* Bs     = Ws + 144 * 144;                       // 144
  float* embS   = Bs + 144;                             // 528

  const int tid  = threadIdx.x;
  const int row0 = blockIdx.x * ROWS;

  // ---- stage state tile (zero-fill OOB rows so card indices stay valid) ----
  for (int e = tid; e < ROWS * 50; e += TPB) {
    int r = e / 50, c = e - r * 50;
    float v = 0.f;
    if (row0 + r < p.nrows) v = p.state[(size_t)(row0 + r) * 50 + c];
    stateS[r * SSTR + c] = v;
  }
  // ---- stage all small embedding tables + first-layer weights ----
  cp_f(embS + EO_SUIT,   p.suit_emb,   40, tid);
  cp_f(embS + EO_RANK,   p.rank_emb,  112, tid);
  cp_f(embS + EO_POS,    p.pos_emb,    56, tid);
  cp_f(embS + EO_ACTION, p.action_emb, 96, tid);
  cp_f(embS + EO_ACTIVE, p.active_emb, 16, tid);
  cp_f(embS + EO_STREET, p.street_emb, 40, tid);
  cp_f(embS + EO_NUMP,   p.nump_emb,   56, tid);
  cp_f(embS + EO_BLIND,  p.blind_emb,  16, tid);
  cp_f(embS + EO_SW,     p.scalar_W,   48, tid);
  cp_f(embS + EO_SB,     p.scalar_b,   48, tid);
  cp_f4(Ws, p.hW1, 64 * 64, tid);
  cp_f(Bs, p.hb1, 64, tid);
  __syncthreads();

  // ---- build card inputs: X[:,0:64] = hand (4 cards), X[:,64:144] = board (5 cards) ----
  // per card: [suit_emb(8), rank_emb(8)]; rank col = 2*card, suit col = 2*card+1
  for (int e = tid; e < ROWS * 144; e += TPB) {
    int r = e / 144, c = e - r * 144;
    int card = c >> 4, t = c & 15;
    float v;
    if (t < 8) {
      int s = (int)stateS[r * SSTR + 2 * card + 1];
      v = embS[EO_SUIT + s * 8 + t];
    } else {
      int rk = (int)stateS[r * SSTR + 2 * card];
      v = embS[EO_RANK + rk * 8 + (t - 8)];
    }
    X[r * XSTR + c] = v;
  }
  __syncthreads();

  // ---- hand/board MLPs, ping-pong X<->Y; hb concat is free (contiguous cols) ----
  gemm_tile<64, 64, 4, true >(X,      Y,      Ws, Bs, tid);  __syncthreads();
  cp_f4(Ws, p.bW1, 80 * 80, tid); cp_f(Bs, p.bb1, 80, tid);  __syncthreads();
  gemm_tile<80, 80, 5, true >(X + 64, Y + 64, Ws, Bs, tid);  __syncthreads();
  cp_f4(Ws, p.hW2, 64 * 64, tid); cp_f(Bs, p.hb2, 64, tid);  __syncthreads();
  gemm_tile<64, 64, 4, true >(Y,      X,      Ws, Bs, tid);  __syncthreads();
  cp_f4(Ws, p.bW2, 80 * 80, tid); cp_f(Bs, p.bb2, 80, tid);  __syncthreads();
  gemm_tile<80, 80, 5, true >(Y + 64, X + 64, Ws, Bs, tid);  __syncthreads();
  cp_f4(Ws, p.hW3, 64 * 64, tid); cp_f(Bs, p.hb3, 64, tid);  __syncthreads();
  gemm_tile<64, 64, 4, false>(X,      Y,      Ws, Bs, tid);  __syncthreads();
  cp_f4(Ws, p.bW3, 80 * 80, tid); cp_f(Bs, p.bb3, 80, tid);  __syncthreads();
  gemm_tile<80, 80, 5, false>(X + 64, Y + 64, Ws, Bs, tid);  __syncthreads();
  // hb MLP: in = Y[:,0:144]
  cp_f4(Ws, p.cW1, 144 * 144, tid); cp_f(Bs, p.cb1, 144, tid); __syncthreads();
  gemm_tile<144, 144, 9, true >(Y, X, Ws, Bs, tid);            __syncthreads();
  cp_f4(Ws, p.cW2, 144 * 64, tid);  cp_f(Bs, p.cb2, 64, tid);  __syncthreads();
  gemm_tile<144, 64, 4, true >(X, Y, Ws, Bs, tid);             __syncthreads();
  cp_f4(Ws, p.cW3, 64 * 64, tid);   cp_f(Bs, p.cb3, 64, tid);  __syncthreads();
  gemm_tile<64, 64, 4, false>(Y, X, Ws, Bs, tid);              __syncthreads();
  // final hand_board result now in X[:,0:64]

  // ---- assemble 312-float output rows (coalesced) ----
  size_t obase = (size_t)row0 * 312;
  for (int e = tid; e < ROWS * 312; e += TPB) {
    int r = e / 312, c = e - r * 312;
    if (row0 + r >= p.nrows) continue;
    float v;
    if (c < 64) {
      v = X[r * XSTR + c];
    } else {
      int s = (c - 64) >> 3, j = (c - 64) & 7;
      int base = c_seg_base[s];
      float sv = stateS[r * SSTR + c_seg_col[s]];
      if (base >= 0) {
        int idx = (int)sv;
        v = embS[base + idx * 8 + j];
      } else {
        int w = -base - 1;
        v = fmaf(sv, embS[EO_SW + w * 8 + j], embS[EO_SB + w * 8 + j]);
      }
    }
    p.out[obase + e] = v;
  }
}

extern "C" void kernel_launch(void* const* d_in, const int* in_sizes, int n_in,
                              void* d_out, int out_size)
{
  Params p;
  p.state      = (const float*)d_in[0];
  p.suit_emb   = (const float*)d_in[1];
  p.rank_emb   = (const float*)d_in[2];
  p.hW1 = (const float*)d_in[3];  p.hb1 = (const float*)d_in[4];
  p.hW2 = (const float*)d_in[5];  p.hb2 = (const float*)d_in[6];
  p.hW3 = (const float*)d_in[7];  p.hb3 = (const float*)d_in[8];
  p.bW1 = (const float*)d_in[9];  p.bb1 = (const float*)d_in[10];
  p.bW2 = (const float*)d_in[11]; p.bb2 = (const float*)d_in[12];
  p.bW3 = (const float*)d_in[13]; p.bb3 = (const float*)d_in[14];
  p.cW1 = (const float*)d_in[15]; p.cb1 = (const float*)d_in[16];
  p.cW2 = (const float*)d_in[17]; p.cb2 = (const float*)d_in[18];
  p.cW3 = (const float*)d_in[19]; p.cb3 = (const float*)d_in[20];
  p.pos_emb    = (const float*)d_in[21];
  p.action_emb = (const float*)d_in[22];
  p.active_emb = (const float*)d_in[23];
  p.street_emb = (const float*)d_in[24];
  p.nump_emb   = (const float*)d_in[25];
  p.blind_emb  = (const float*)d_in[26];
  p.scalar_W   = (const float*)d_in[27];
  p.scalar_b   = (const float*)d_in[28];
  p.out   = (float*)d_out;
  p.nrows = in_sizes[0] / 50;

  const int smem_bytes =
      (ROWS * SSTR + 2 * ROWS * XSTR + 144 * 144 + 144 + EO_TOTAL) * (int)sizeof(float);
  cudaFuncSetAttribute(PreProcess_kernel,
                       cudaFuncAttributeMaxDynamicSharedMemorySize, smem_bytes);

  int grid = (p.nrows + ROWS - 1) / ROWS;
  PreProcess_kernel<<<grid, TPB, smem_bytes>>>(p);
}